// round 13
// baseline (speedup 1.0000x reference)
#include <cuda_runtime.h>
#include <cuda_bf16.h>
#include <math_constants.h>
#include <cstdint>

typedef unsigned long long u64;

#define EMBED  512
#define HEADS  2
#define HDIM   256
#define NTXT   4096
#define NVID   768
#define FRAMES 12
#define VIDS   64

#define BM 128
#define BN 128
#define BK 32
#define LDT 40                       // 32 + 8 pad bf16 -> 80B row stride (16B-mult, ldmatrix conflict-free)

static const int TILE_B  = 128 * LDT * 2;   // 10240 B per tile
static const int STAGE_B = 4 * TILE_B;      // Ah, Al, Bh, Bl
static const int SMEM_SZ = 2 * STAGE_B;     // 81920 B double-buffered (2 CTAs/SM)

// ---------------- device scratch ----------------
// g_s doubles as: logits S'[h][t][v] (2*4096*768 f32), then attn split-K
// partials (3*4096*512 f32) -- identical sizes, sequential lifetimes.
__device__ float g_s    [HEADS*(size_t)NTXT*NVID];
__device__ float g_o    [NTXT*EMBED];
__device__ float g_wop  [2*(size_t)NTXT*EMBED];   // Wo split-K partials
__device__ float g_linp [2*(size_t)NTXT*EMBED];   // Wl split-K partials

__device__ __nv_bfloat16 g_tln_h[NTXT*EMBED],  g_tln_l[NTXT*EMBED];
__device__ __nv_bfloat16 g_vln_h[NVID*EMBED],  g_vln_l[NVID*EMBED];
__device__ __nv_bfloat16 g_q_h [NTXT*EMBED],   g_q_l [NTXT*EMBED];
__device__ __nv_bfloat16 g_k_h [NVID*EMBED],   g_k_l [NVID*EMBED];
__device__ __nv_bfloat16 g_vt_h[EMBED*NVID],   g_vt_l[EMBED*NVID];
__device__ __nv_bfloat16 g_p_h [HEADS*(size_t)NTXT*NVID], g_p_l[HEADS*(size_t)NTXT*NVID];
__device__ __nv_bfloat16 g_at_h[NTXT*EMBED],   g_at_l[NTXT*EMBED];
__device__ __nv_bfloat16 g_o_h [NTXT*EMBED],   g_o_l [NTXT*EMBED];
__device__ __nv_bfloat16 g_wq_h[EMBED*EMBED],  g_wq_l[EMBED*EMBED];
__device__ __nv_bfloat16 g_wk_h[EMBED*EMBED],  g_wk_l[EMBED*EMBED];
__device__ __nv_bfloat16 g_wv_h[EMBED*EMBED],  g_wv_l[EMBED*EMBED];
__device__ __nv_bfloat16 g_wo_h[EMBED*EMBED],  g_wo_l[EMBED*EMBED];
__device__ __nv_bfloat16 g_wl_h[EMBED*EMBED],  g_wl_l[EMBED*EMBED];

// ---------------- PTX helpers ----------------
__device__ __forceinline__ uint32_t smem_u32(const void* p) {
    uint32_t a;
    asm("{ .reg .u64 t; cvta.to.shared.u64 t, %1; cvt.u32.u64 %0, t; }" : "=r"(a) : "l"(p));
    return a;
}
__device__ __forceinline__ void cpa16(uint32_t d, const void* g) {
    asm volatile("cp.async.cg.shared.global [%0], [%1], 16;" :: "r"(d), "l"(g));
}
__device__ __forceinline__ void ldsm4(uint32_t& r0, uint32_t& r1, uint32_t& r2, uint32_t& r3,
                                      uint32_t a) {
    asm volatile("ldmatrix.sync.aligned.m8n8.x4.shared.b16 {%0,%1,%2,%3}, [%4];"
                 : "=r"(r0), "=r"(r1), "=r"(r2), "=r"(r3) : "r"(a));
}
__device__ __forceinline__ void mma_bf16(float* c, const uint32_t* a, const uint32_t* b) {
    asm volatile("mma.sync.aligned.m16n8k16.row.col.f32.bf16.bf16.f32 "
                 "{%0,%1,%2,%3}, {%4,%5,%6,%7}, {%8,%9}, {%0,%1,%2,%3};"
                 : "+f"(c[0]), "+f"(c[1]), "+f"(c[2]), "+f"(c[3])
                 : "r"(a[0]), "r"(a[1]), "r"(a[2]), "r"(a[3]), "r"(b[0]), "r"(b[1]));
}
__device__ __forceinline__ void split_bf16(float v, __nv_bfloat16& h, __nv_bfloat16& l) {
    h = __float2bfloat16(v);
    l = __float2bfloat16(v - __bfloat162float(h));
}

// ============================================================
// HMMA NT GEMM core (R11 winner, unchanged).
// ============================================================
template<int BIASM, bool WF32, bool WB16>
__device__ __forceinline__ void mm_core(
    const __nv_bfloat16* __restrict__ Ah, const __nv_bfloat16* __restrict__ Al, int lda,
    const __nv_bfloat16* __restrict__ Bh, const __nv_bfloat16* __restrict__ Bl, int ldb,
    const float* __restrict__ bias,
    float* __restrict__ Cf, __nv_bfloat16* __restrict__ Ch, __nv_bfloat16* __restrict__ Cl,
    int ldc, int K, float alpha, int m0, int n0, char* smem)
{
    const uint32_t sb = smem_u32(smem);
    const int tid = threadIdx.x, wid = tid >> 5, lane = tid & 31;

    const int mw = (wid & 3) * 32;
    const int nw = (wid >> 2) * 64;
    const int lr = tid >> 2;
    const int lc = (tid & 3) * 8;

    auto load_stage = [&](int s, int buf) {
        const int kb = s * BK;
#pragma unroll
        for (int t = 0; t < 4; t++) {
            const __nv_bfloat16* sp = (t == 0) ? Ah : (t == 1) ? Al : (t == 2) ? Bh : Bl;
            const int r0g = (t < 2) ? m0 : n0;
            const int ld  = (t < 2) ? lda : ldb;
            const uint32_t db = sb + buf * STAGE_B + t * TILE_B;
#pragma unroll
            for (int p = 0; p < 2; p++) {
                const int r = lr + p * 64;
                cpa16(db + (r * LDT + lc) * 2,
                      sp + (size_t)(r0g + r) * ld + kb + lc);
            }
        }
        asm volatile("cp.async.commit_group;" ::: "memory");
    };

    float acc[2][8][4];
#pragma unroll
    for (int i = 0; i < 2; i++)
#pragma unroll
        for (int j = 0; j < 8; j++)
#pragma unroll
            for (int r = 0; r < 4; r++) acc[i][j][r] = 0.f;

    const int row_a = lane & 15;
    const int ka    = (lane >> 4) * 8;
    const int row_b = (lane & 7) + ((lane & 16) >> 1);
    const int kb_   = lane & 8;

    const int S = K / BK;
    int buf = 0;
    load_stage(0, 0);

    for (int s = 0; s < S; s++) {
        if (s + 1 < S) {
            load_stage(s + 1, buf ^ 1);
            asm volatile("cp.async.wait_group 1;" ::: "memory");
        } else {
            asm volatile("cp.async.wait_group 0;" ::: "memory");
        }
        __syncthreads();

        const uint32_t abh = sb + buf * STAGE_B;
        const uint32_t abl = abh + TILE_B;
        const uint32_t bbh = abh + 2 * TILE_B;
        const uint32_t bbl = abh + 3 * TILE_B;

#pragma unroll
        for (int kk = 0; kk < 2; kk++) {
            const int k0 = kk * 16;
            uint32_t ah[2][4], al_[2][4];
#pragma unroll
            for (int mf = 0; mf < 2; mf++) {
                const uint32_t off = ((mw + mf * 16 + row_a) * LDT + k0 + ka) * 2;
                ldsm4(ah[mf][0], ah[mf][1], ah[mf][2], ah[mf][3], abh + off);
                ldsm4(al_[mf][0], al_[mf][1], al_[mf][2], al_[mf][3], abl + off);
            }
#pragma unroll
            for (int h2 = 0; h2 < 2; h2++) {
                uint32_t bh[4][2], bl_[4][2];
#pragma unroll
                for (int p = 0; p < 2; p++) {
                    const int pp = h2 * 2 + p;
                    const uint32_t off = ((nw + pp * 16 + row_b) * LDT + k0 + kb_) * 2;
                    ldsm4(bh[2*p][0], bh[2*p][1], bh[2*p+1][0], bh[2*p+1][1], bbh + off);
                    ldsm4(bl_[2*p][0], bl_[2*p][1], bl_[2*p+1][0], bl_[2*p+1][1], bbl + off);
                }
#pragma unroll
                for (int mf = 0; mf < 2; mf++)
#pragma unroll
                    for (int nf = 0; nf < 4; nf++) {
                        float* a4 = acc[mf][h2 * 4 + nf];
                        mma_bf16(a4, ah[mf],  bh[nf]);
                        mma_bf16(a4, ah[mf],  bl_[nf]);
                        mma_bf16(a4, al_[mf], bh[nf]);
                    }
            }
        }
        __syncthreads();
        buf ^= 1;
    }

    // ---- epilogue ----
    const int er = lane >> 2, ec = (lane & 3) * 2;
#pragma unroll
    for (int mf = 0; mf < 2; mf++) {
#pragma unroll
        for (int rh = 0; rh < 2; rh++) {
            const int m = m0 + mw + mf * 16 + er + rh * 8;
            const float bm = (BIASM == 2) ? __ldg(bias + m) : 0.f;
#pragma unroll
            for (int nf = 0; nf < 8; nf++) {
                const int n = n0 + nw + nf * 8 + ec;
                float v0 = acc[mf][nf][rh * 2]     * alpha;
                float v1 = acc[mf][nf][rh * 2 + 1] * alpha;
                if (BIASM == 1) { v0 += __ldg(bias + n); v1 += __ldg(bias + n + 1); }
                if (BIASM == 2) { v0 += bm; v1 += bm; }
                if (WF32)
                    *(float2*)(Cf + (size_t)m * ldc + n) = make_float2(v0, v1);
                if (WB16) {
                    __nv_bfloat16 h0, l0, h1, l1;
                    split_bf16(v0, h0, l0);
                    split_bf16(v1, h1, l1);
                    __nv_bfloat162 hh(h0, h1), ll(l0, l1);
                    *(uint32_t*)(Ch + (size_t)m * ldc + n) = *(uint32_t*)&hh;
                    *(uint32_t*)(Cl + (size_t)m * ldc + n) = *(uint32_t*)&ll;
                }
            }
        }
    }
}

// ---- generic GEMM wrapper (z batches A/B/C by element strides) ----
template<int BIASM, bool WF32, bool WB16>
__global__ __launch_bounds__(256, 2) void mm_kernel(
    const __nv_bfloat16* __restrict__ Ah, const __nv_bfloat16* __restrict__ Al,
    int lda, size_t zsA,
    const __nv_bfloat16* __restrict__ Bh, const __nv_bfloat16* __restrict__ Bl,
    int ldb, size_t zsB,
    const float* __restrict__ bias,
    float* __restrict__ Cf, __nv_bfloat16* __restrict__ Ch, __nv_bfloat16* __restrict__ Cl,
    int ldc, size_t zsC,
    int K, float alpha)
{
    extern __shared__ char smem[];
    const int z = blockIdx.z;
    Ah += z * zsA;  Al += z * zsA;
    Bh += z * zsB;  Bl += z * zsB;
    if (WF32) Cf += z * zsC;
    if (WB16) { Ch += z * zsC; Cl += z * zsC; }
    mm_core<BIASM, WF32, WB16>(Ah, Al, lda, Bh, Bl, ldb, bias, Cf, Ch, Cl,
                               ldc, K, alpha, blockIdx.y * BM, blockIdx.x * BN, smem);
}

// fused Q / K / Vt projections (z = 0:Q, 1:K, 2:Vt), per-job grid guards
__global__ __launch_bounds__(256, 2) void qkv_kernel(
    const __nv_bfloat16* __restrict__ tlnh, const __nv_bfloat16* __restrict__ tlnl,
    const __nv_bfloat16* __restrict__ vlnh, const __nv_bfloat16* __restrict__ vlnl,
    const __nv_bfloat16* __restrict__ wqh,  const __nv_bfloat16* __restrict__ wql,
    const __nv_bfloat16* __restrict__ wkh,  const __nv_bfloat16* __restrict__ wkl,
    const __nv_bfloat16* __restrict__ wvh,  const __nv_bfloat16* __restrict__ wvl,
    const float* __restrict__ bq, const float* __restrict__ bk, const float* __restrict__ bv,
    __nv_bfloat16* __restrict__ qh,  __nv_bfloat16* __restrict__ ql,
    __nv_bfloat16* __restrict__ kh,  __nv_bfloat16* __restrict__ kl,
    __nv_bfloat16* __restrict__ vth, __nv_bfloat16* __restrict__ vtl)
{
    extern __shared__ char smem[];
    const int z = blockIdx.z;
    const int bx = blockIdx.x, by = blockIdx.y;
    const int m0 = by * BM, n0 = bx * BN;
    if (z == 0) {
        if (bx >= EMBED / BN || by >= NTXT / BM) return;
        mm_core<1,false,true>(tlnh, tlnl, EMBED, wqh, wql, EMBED, bq,
                              nullptr, qh, ql, EMBED, EMBED, 1.f, m0, n0, smem);
    } else if (z == 1) {
        if (bx >= EMBED / BN || by >= NVID / BM) return;
        mm_core<1,false,true>(vlnh, vlnl, EMBED, wkh, wkl, EMBED, bk,
                              nullptr, kh, kl, EMBED, EMBED, 1.f, m0, n0, smem);
    } else {
        if (bx >= NVID / BN || by >= EMBED / BM) return;
        mm_core<2,false,true>(wvh, wvl, EMBED, vlnh, vlnl, EMBED, bv,
                              nullptr, vth, vtl, NVID, EMBED, 1.f, m0, n0, smem);
    }
}

// attn split-K: z = head*3 + ks.  Each slice contracts 256 of K=768,
// writes fp32 partial slab ks (aliased over g_s).
__global__ __launch_bounds__(256, 2) void attn_kernel(
    const __nv_bfloat16* __restrict__ ph, const __nv_bfloat16* __restrict__ pl,
    const __nv_bfloat16* __restrict__ vth, const __nv_bfloat16* __restrict__ vtl,
    float* __restrict__ part)
{
    extern __shared__ char smem[];
    const int z = blockIdx.z;
    const int head = z / 3, ks = z % 3;
    const size_t aoff = (size_t)head * NTXT * NVID + ks * 256;
    const size_t boff = (size_t)head * HDIM * NVID + ks * 256;
    float* Cf = part + (size_t)ks * NTXT * EMBED + head * HDIM;
    mm_core<0,true,false>(ph + aoff, pl + aoff, NVID,
                          vth + boff, vtl + boff, NVID, nullptr,
                          Cf, nullptr, nullptr, EMBED, 256, 1.f / 64.f,
                          blockIdx.y * BM, blockIdx.x * BN, smem);
}

// sum 3 fp32 partial slabs -> bf16 hi/lo attn
__global__ __launch_bounds__(256) void reduce3_k(
    const float* __restrict__ p, __nv_bfloat16* __restrict__ h, __nv_bfloat16* __restrict__ l)
{
    const size_t slab = (size_t)NTXT * EMBED;
    int i = (blockIdx.x * 256 + threadIdx.x) * 2;
    float2 a = *(const float2*)(p + i);
    float2 b = *(const float2*)(p + slab + i);
    float2 c = *(const float2*)(p + 2 * slab + i);
    float v0 = a.x + b.x + c.x, v1 = a.y + b.y + c.y;
    __nv_bfloat16 h0, l0, h1, l1;
    split_bf16(v0, h0, l0);
    split_bf16(v1, h1, l1);
    __nv_bfloat162 hh(h0, h1), ll(l0, l1);
    *(uint32_t*)(h + i) = *(uint32_t*)&hh;
    *(uint32_t*)(l + i) = *(uint32_t*)&ll;
}

// ============================================================
// LayerNorm (rows of 512). NADD fp32 addends + optional per-column bias
// vector (applied pre-normalization); fp32 / bf16-hi/lo outputs.
// ============================================================
template<int NADD, bool CB, bool W32, bool W16>
__device__ __forceinline__ void ln_core(
    const float* __restrict__ x, const float* __restrict__ x2, const float* __restrict__ x3,
    const float* __restrict__ cb,
    float* __restrict__ yf, __nv_bfloat16* __restrict__ yh, __nv_bfloat16* __restrict__ yl,
    const float* __restrict__ g, const float* __restrict__ b, int row)
{
    int t = threadIdx.x;
    float2 v = ((const float2*)(x + (size_t)row * EMBED))[t];
    if (NADD >= 2) {
        float2 w = ((const float2*)(x2 + (size_t)row * EMBED))[t];
        v.x += w.x; v.y += w.y;
    }
    if (NADD >= 3) {
        float2 w = ((const float2*)(x3 + (size_t)row * EMBED))[t];
        v.x += w.x; v.y += w.y;
    }
    if (CB) {
        float2 w = ((const float2*)cb)[t];
        v.x += w.x; v.y += w.y;
    }
    float s = v.x + v.y, s2 = v.x * v.x + v.y * v.y;
#pragma unroll
    for (int o = 16; o; o >>= 1) {
        s  += __shfl_xor_sync(0xffffffffu, s,  o);
        s2 += __shfl_xor_sync(0xffffffffu, s2, o);
    }
    __shared__ float rs[8], rs2[8];
    if ((t & 31) == 0) { rs[t >> 5] = s; rs2[t >> 5] = s2; }
    __syncthreads();
    if (t < 32) {
        float a  = t < 8 ? rs[t]  : 0.f;
        float a2 = t < 8 ? rs2[t] : 0.f;
#pragma unroll
        for (int o = 4; o; o >>= 1) {
            a  += __shfl_xor_sync(0xffffffffu, a,  o);
            a2 += __shfl_xor_sync(0xffffffffu, a2, o);
        }
        if (t == 0) { rs[0] = a; rs2[0] = a2; }
    }
    __syncthreads();
    float mu  = rs[0]  * (1.f / EMBED);
    float var = rs2[0] * (1.f / EMBED) - mu * mu;
    float inv = rsqrtf(var + 1e-5f);
    float2 gg = ((const float2*)g)[t], bb = ((const float2*)b)[t];
    float2 r = make_float2((v.x - mu) * inv * gg.x + bb.x,
                           (v.y - mu) * inv * gg.y + bb.y);
    if (W32) ((float2*)(yf + (size_t)row * EMBED))[t] = r;
    if (W16) {
        __nv_bfloat16 h0, l0, h1, l1;
        split_bf16(r.x, h0, l0);
        split_bf16(r.y, h1, l1);
        __nv_bfloat162 hh(h0, h1), ll(l0, l1);
        ((uint32_t*)(yh + (size_t)row * EMBED))[t] = *(uint32_t*)&hh;
        ((uint32_t*)(yl + (size_t)row * EMBED))[t] = *(uint32_t*)&ll;
    }
}

template<int NADD, bool CB, bool W32, bool W16>
__global__ __launch_bounds__(256) void ln_k(
    const float* __restrict__ x, const float* __restrict__ x2, const float* __restrict__ x3,
    const float* __restrict__ cb,
    float* __restrict__ yf, __nv_bfloat16* __restrict__ yh, __nv_bfloat16* __restrict__ yl,
    const float* __restrict__ g, const float* __restrict__ b)
{
    ln_core<NADD, CB, W32, W16>(x, x2, x3, cb, yf, yh, yl, g, b, blockIdx.x);
}

// fused LN1 over text (rows 0..4095) + video (rows 4096..4863)
__global__ __launch_bounds__(256) void ln1_k(
    const float* __restrict__ text, const float* __restrict__ video,
    __nv_bfloat16* __restrict__ tlnh, __nv_bfloat16* __restrict__ tlnl,
    __nv_bfloat16* __restrict__ vlnh, __nv_bfloat16* __restrict__ vlnl,
    const float* __restrict__ g, const float* __restrict__ b)
{
    int row = blockIdx.x;
    if (row < NTXT)
        ln_core<1,false,false,true>(text, nullptr, nullptr, nullptr,
                                    nullptr, tlnh, tlnl, g, b, row);
    else
        ln_core<1,false,false,true>(video, nullptr, nullptr, nullptr,
                                    nullptr, vlnh, vlnl, g, b, row - NTXT);
}

// ============================================================
// Softmax over 12 contiguous frames: S'[h][t][a*12+f] -> P hi/lo bf16.
// ============================================================
__global__ __launch_bounds__(256) void softmax_k(
    const float* __restrict__ S, __nv_bfloat16* __restrict__ Ph, __nv_bfloat16* __restrict__ Pl)
{
    int idx = blockIdx.x * 256 + threadIdx.x;
    size_t off = (size_t)(idx >> 6) * NVID + (idx & 63) * FRAMES;
    const float* base = S + off;
    float4 v0 = *(const float4*)(base);
    float4 v1 = *(const float4*)(base + 4);
    float4 v2 = *(const float4*)(base + 8);
    float vl[12] = {v0.x,v0.y,v0.z,v0.w, v1.x,v1.y,v1.z,v1.w, v2.x,v2.y,v2.z,v2.w};
    float m = -CUDART_INF_F;
#pragma unroll
    for (int f = 0; f < 12; f++) m = fmaxf(m, vl[f]);
    float sum = 0.f;
#pragma unroll
    for (int f = 0; f < 12; f++) { vl[f] = __expf(vl[f] - m); sum += vl[f]; }
    float inv = 1.f / sum;
    uint32_t hp[6], lp[6];
#pragma unroll
    for (int g = 0; g < 6; g++) {
        __nv_bfloat16 h0, l0, h1, l1;
        split_bf16(vl[2*g]   * inv, h0, l0);
        split_bf16(vl[2*g+1] * inv, h1, l1);
        __nv_bfloat162 hh(h0, h1), ll(l0, l1);
        hp[g] = *(uint32_t*)&hh;  lp[g] = *(uint32_t*)&ll;
    }
#pragma unroll
    for (int g = 0; g < 3; g++) {
        *(uint2*)(Ph + off + g * 4) = make_uint2(hp[2*g], hp[2*g+1]);
        *(uint2*)(Pl + off + g * 4) = make_uint2(lp[2*g], lp[2*g+1]);
    }
}

// fused fp32 -> bf16 hi/lo converter for ALL 5 weights (grid.y selects weight)
__global__ __launch_bounds__(256) void conv5_k(
    const float* __restrict__ s0, __nv_bfloat16* __restrict__ h0, __nv_bfloat16* __restrict__ l0,
    const float* __restrict__ s1, __nv_bfloat16* __restrict__ h1, __nv_bfloat16* __restrict__ l1,
    const float* __restrict__ s2, __nv_bfloat16* __restrict__ h2, __nv_bfloat16* __restrict__ l2,
    const float* __restrict__ s3, __nv_bfloat16* __restrict__ h3, __nv_bfloat16* __restrict__ l3,
    const float* __restrict__ s4, __nv_bfloat16* __restrict__ h4, __nv_bfloat16* __restrict__ l4)
{
    const float* s; __nv_bfloat16 *h, *l;
    switch (blockIdx.y) {
        case 0: s = s0; h = h0; l = l0; break;
        case 1: s = s1; h = h1; l = l1; break;
        case 2: s = s2; h = h2; l = l2; break;
        case 3: s = s3; h = h3; l = l3; break;
        default: s = s4; h = h4; l = l4; break;
    }
    int i = (blockIdx.x * 256 + threadIdx.x) * 2;
    float2 v = *(const float2*)(s + i);
    __nv_bfloat16 ha, la, hb, lb;
    split_bf16(v.x, ha, la);
    split_bf16(v.y, hb, lb);
    __nv_bfloat162 hh(ha, hb), ll(la, lb);
    *(uint32_t*)(h + i) = *(uint32_t*)&hh;
    *(uint32_t*)(l + i) = *(uint32_t*)&ll;
}

// ============================================================
extern "C" void kernel_launch(void* const* d_in, const int* in_sizes, int n_in,
                              void* d_out, int out_size)
{
    const float* text  = (const float*)d_in[0];
    const float* video = (const float*)d_in[1];
    const float* ln1_g = (const float*)d_in[2];
    const float* ln1_b = (const float*)d_in[3];
    const float* Wq    = (const float*)d_in[4];
    const float* bq    = (const float*)d_in[5];
    const float* Wk    = (const float*)d_in[6];
    const float* bk    = (const float*)d_in[7];
    const float* Wv    = (const float*)d_in[8];
    const float* bv    = (const float*)d_in[9];
    const float* Wo    = (const float*)d_in[10];
    const float* bo    = (const float*)d_in[11];
    const float* Wl    = (const float*)d_in[12];
    const float* bl    = (const float*)d_in[13];
    const float* ln2_g = (const float*)d_in[14];
    const float* ln2_b = (const float*)d_in[15];
    const float* ln3_g = (const float*)d_in[16];
    const float* ln3_b = (const float*)d_in[17];
    float* out = (float*)d_out;

    float *s, *o, *wop, *linp;
    __nv_bfloat16 *tlnh,*tlnl,*vlnh,*vlnl,*qh,*ql,*kh,*kl,*vth,*vtl,*ph,*pl,*ath,*atl,*oh,*ol;
    __nv_bfloat16 *wqh,*wql,*wkh,*wkl,*wvh,*wvl,*woh,*wol,*wlh,*wll;
    cudaGetSymbolAddress((void**)&s,    g_s);
    cudaGetSymbolAddress((void**)&o,    g_o);
    cudaGetSymbolAddress((void**)&wop,  g_wop);
    cudaGetSymbolAddress((void**)&linp, g_linp);
    cudaGetSymbolAddress((void**)&tlnh, g_tln_h); cudaGetSymbolAddress((void**)&tlnl, g_tln_l);
    cudaGetSymbolAddress((void**)&vlnh, g_vln_h); cudaGetSymbolAddress((void**)&vlnl, g_vln_l);
    cudaGetSymbolAddress((void**)&qh,  g_q_h);  cudaGetSymbolAddress((void**)&ql,  g_q_l);
    cudaGetSymbolAddress((void**)&kh,  g_k_h);  cudaGetSymbolAddress((void**)&kl,  g_k_l);
    cudaGetSymbolAddress((void**)&vth, g_vt_h); cudaGetSymbolAddress((void**)&vtl, g_vt_l);
    cudaGetSymbolAddress((void**)&ph,  g_p_h);  cudaGetSymbolAddress((void**)&pl,  g_p_l);
    cudaGetSymbolAddress((void**)&ath, g_at_h); cudaGetSymbolAddress((void**)&atl, g_at_l);
    cudaGetSymbolAddress((void**)&oh,  g_o_h);  cudaGetSymbolAddress((void**)&ol,  g_o_l);
    cudaGetSymbolAddress((void**)&wqh, g_wq_h); cudaGetSymbolAddress((void**)&wql, g_wq_l);
    cudaGetSymbolAddress((void**)&wkh, g_wk_h); cudaGetSymbolAddress((void**)&wkl, g_wk_l);
    cudaGetSymbolAddress((void**)&wvh, g_wv_h); cudaGetSymbolAddress((void**)&wvl, g_wv_l);
    cudaGetSymbolAddress((void**)&woh, g_wo_h); cudaGetSymbolAddress((void**)&wol, g_wo_l);
    cudaGetSymbolAddress((void**)&wlh, g_wl_h); cudaGetSymbolAddress((void**)&wll, g_wl_l);

    cudaFuncSetAttribute(qkv_kernel,               cudaFuncAttributeMaxDynamicSharedMemorySize, SMEM_SZ);
    cudaFuncSetAttribute(attn_kernel,              cudaFuncAttributeMaxDynamicSharedMemorySize, SMEM_SZ);
    cudaFuncSetAttribute(mm_kernel<0,true,false>,  cudaFuncAttributeMaxDynamicSharedMemorySize, SMEM_SZ);

    // 0) all 5 weights -> bf16 hi/lo, ONE launch
    conv5_k<<<dim3(EMBED * EMBED / 512, 5), 256>>>(
        Wq, wqh, wql, Wk, wkh, wkl, Wv, wvh, wvl, Wo, woh, wol, Wl, wlh, wll);

    // 1) LN1 text + video, ONE launch
    ln1_k<<<NTXT + NVID, 256>>>(text, video, tlnh, tlnl, vlnh, vlnl, ln1_g, ln1_b);

    // 2) Q / K / Vt projections, ONE launch; grid = max over jobs, guarded per job
    qkv_kernel<<<dim3(NVID/BN, NTXT/BM, 3), 256, SMEM_SZ>>>(
        tlnh, tlnl, vlnh, vlnl, wqh, wql, wkh, wkl, wvh, wvl,
        bq, bk, bv, qh, ql, kh, kl, vth, vtl);

    // 3) logits S'[h][t][v] = (1/16) Q_h @ K_h^T  [4096x768], z = head
    mm_kernel<0,true,false><<<dim3(NVID/BN, NTXT/BM, HEADS), 256, SMEM_SZ>>>(
        qh, ql, EMBED, (size_t)HDIM, kh, kl, EMBED, (size_t)HDIM, nullptr,
        s, nullptr, nullptr, NVID, (size_t)NTXT*NVID, HDIM, 1.f/16.f);

    // 4) softmax over 12 frames -> P hi/lo
    softmax_k<<<(HEADS * NTXT * VIDS) / 256, 256>>>(s, ph, pl);

    // 5) attn split-K x3 (grid 384 = full waves), partials alias g_s
    attn_kernel<<<dim3(HDIM/BN, NTXT/BM, HEADS * 3), 256, SMEM_SZ>>>(
        ph, pl, vth, vtl, s);
    reduce3_k<<<NTXT * EMBED / 512, 256>>>(s, ath, atl);

    // 6) Wo projection, split-K x2 -> partials; LN2 sums them + bias bo
    mm_kernel<0,true,false><<<dim3(EMBED/BN, NTXT/BM, 2), 256, SMEM_SZ>>>(
        ath, atl, EMBED, (size_t)256, woh, wol, EMBED, (size_t)256, nullptr,
        wop, nullptr, nullptr, EMBED, (size_t)NTXT*EMBED, 256, 1.f);
    ln_k<2,true,true,true><<<NTXT, 256>>>(wop, wop + (size_t)NTXT*EMBED, nullptr, bo,
                                          o, oh, ol, ln2_g, ln2_b);

    // 7) Wl linear, split-K x2 -> partials; LN3 sums o + both partials + bias bl
    mm_kernel<0,true,false><<<dim3(EMBED/BN, NTXT/BM, 2), 256, SMEM_SZ>>>(
        oh, ol, EMBED, (size_t)256, wlh, wll, EMBED, (size_t)256, nullptr,
        linp, nullptr, nullptr, EMBED, (size_t)NTXT*EMBED, 256, 1.f);
    ln_k<3,true,true,false><<<NTXT, 256>>>(o, linp, linp + (size_t)NTXT*EMBED, bl,
                                           out, nullptr, nullptr, ln3_g, ln3_b);
}